// round 16
// baseline (speedup 1.0000x reference)
#include <cuda_runtime.h>
#include <cstdint>
#include <math.h>

#define TT 64
#define NB 32
#define CC 128
#define DD 64
#define NC (NB * CC)

typedef unsigned long long u64;

// per-(n,c): 64-bit integrator-spike word over t (si = any jeffress spike)
__device__ u64 g_si[NC];

#define BAR_ARRIVE(id, cnt) asm volatile("bar.arrive %0, %1;" :: "r"(id), "r"(cnt) : "memory")
#define BAR_SYNC(id, cnt)   asm volatile("bar.sync %0, %1;"   :: "r"(id), "r"(cnt) : "memory")

// ---------------------------------------------------------------------------
// K1: warp per (n,c), per-t VOTE.ANY (R7/R10 verified structure).
// Exact shortcut: every kint > 1 and the integrator IF hard-resets, so the
// integrator spike si_t == (any unit spiked at t).
// Input fold (R15): u = ab?2:(ao?1:0) with ao=a|d, ab=a&d — exact values.
// New: t-loop runs on 32-bit half-words (extracts + siw OR are single
// 32-bit LOP3s instead of paired-register u64 ops).
// ---------------------------------------------------------------------------
__global__ void __launch_bounds__(256) k1_lif(const float* __restrict__ x)
{
    const unsigned FULL = 0xFFFFFFFFu;
    const int tid  = threadIdx.x;
    const int lane = tid & 31;
    const int wg   = (blockIdx.x * blockDim.x + tid) >> 5;  // nc
    const int n = wg >> 7;
    const int c = wg & (CC - 1);

    // pack input spikes: bit t of bx = x[t] != 0
    const int base = n * 2 * CC + c;
    const int strideT = NB * 2 * CC;
    unsigned lo0 = __ballot_sync(FULL, x[base + lane * strideT]             != 0.0f);
    unsigned hi0 = __ballot_sync(FULL, x[base + (lane + 32) * strideT]      != 0.0f);
    unsigned lo1 = __ballot_sync(FULL, x[base + CC + lane * strideT]        != 0.0f);
    unsigned hi1 = __ballot_sync(FULL, x[base + CC + (lane + 32) * strideT] != 0.0f);
    u64 bx0 = (u64)lo0 | ((u64)hi0 << 32);
    u64 bx1 = (u64)lo1 | ((u64)hi1 << 32);

    // unit j sees x0 delayed by j, x1 delayed by (D-1-j): pre-shift
    u64 a0 = bx0 << lane;            // unit j0 = lane
    u64 a1 = bx0 << (lane + 32);     // unit j1 = lane + 32
    u64 d0 = bx1 << (63 - lane);
    u64 d1 = bx1 << (31 - lane);

    // fold: sum of 2 bits -> OR/AND words, split into 32-bit halves
    u64 ao0 = a0 | d0, ab0 = a0 & d0;
    u64 ao1 = a1 | d1, ab1 = a1 & d1;
    unsigned ao0h[2] = { (unsigned)ao0, (unsigned)(ao0 >> 32) };
    unsigned ab0h[2] = { (unsigned)ab0, (unsigned)(ab0 >> 32) };
    unsigned ao1h[2] = { (unsigned)ao1, (unsigned)(ao1 >> 32) };
    unsigned ab1h[2] = { (unsigned)ab1, (unsigned)(ab1 >> 32) };

    float vj0 = 0.0f, vj1 = 0.0f;
    unsigned siwh[2] = { 0u, 0u };

    #pragma unroll
    for (int half = 0; half < 2; ++half) {
        const unsigned qao0 = ao0h[half], qab0 = ab0h[half];
        const unsigned qao1 = ao1h[half], qab1 = ab1h[half];
        unsigned sw = 0u;
        #pragma unroll
        for (int tt = 0; tt < 32; ++tt) {
            float u0 = ((qab0 >> tt) & 1u) ? 2.0f : (((qao0 >> tt) & 1u) ? 1.0f : 0.0f);
            float u1 = ((qab1 >> tt) & 1u) ? 2.0f : (((qao1 >> tt) & 1u) ? 1.0f : 0.0f);
            vj0 = fmaf(u0 - vj0, 0.05f, vj0);
            vj1 = fmaf(u1 - vj1, 0.05f, vj1);
            bool s0 = (vj0 >= 1.0f), s1 = (vj1 >= 1.0f);
            bool any = __any_sync(FULL, s0 | s1);
            vj0 = s0 ? 0.0f : vj0;
            vj1 = s1 ? 0.0f : vj1;
            sw |= any ? (1u << tt) : 0u;
        }
        siwh[half] = sw;
    }

    if (lane == 0) g_si[wg] = (u64)siwh[0] | ((u64)siwh[1] << 32);
}

// ---------------------------------------------------------------------------
// K2K3 (R14 verbatim — best measured at 10.91us): one block per n, 256
// threads, warp-specialized chunk pipeline (chunk = 16 timesteps, 4 chunks).
// Barrier audit:
//   id 1+c : producers (warps 0-3) 128 arrive + warp 4 32 sync  = 160
//   id 5+c : warp 4 32 arrive + warps 5,6 64 sync               = 96
//   id 9+c : warps 5,6 64 arrive + warp 7 32 sync               = 96
// Producers emit per-(warp,t) partial spike counts via a 16-ballot
// transpose; Phase S dsum via select + balanced add tree (in registers).
// ---------------------------------------------------------------------------
__global__ void __launch_bounds__(256, 1) k2k3(
    const float* __restrict__ w1, const float* __restrict__ b1,
    const float* __restrict__ w2, const float* __restrict__ b2,
    const float* __restrict__ sw0, const float* __restrict__ sb0,
    const float* __restrict__ sw1, const float* __restrict__ sb1,
    const float* __restrict__ sw2, const float* __restrict__ sb2,
    float* __restrict__ out)
{
    __shared__ int pcnt[4][4][16];       // [chunk][producer warp][t]
    __shared__ unsigned sa_masks[TT];
    __shared__ float sw1s[32 * 33];
    __shared__ float msb[TT][33];
    __shared__ float qbuf[TT][33];

    const unsigned FULL = 0xFFFFFFFFu;
    const int n = blockIdx.x;
    const int tid = threadIdx.x;
    const int lane = tid & 31;
    const int wid = tid >> 5;

    #pragma unroll
    for (int i = tid; i < 1024; i += 256) {
        int row = i >> 5, col = i & 31;
        sw1s[row * 33 + col] = sw1[i];
    }
    __syncthreads();

    if (wid < 4) {
        // ---- Phase S producers: thread = channel (tid 0..127) ----
        float w1r[10], b1r[10], w2r[10];
        #pragma unroll
        for (int i = 0; i < 10; ++i) { w1r[i] = w1[i]; b1r[i] = b1[i]; w2r[i] = w2[i]; }
        const float b2v = b2[0];
        float babs = fabsf(b2v);
        #pragma unroll
        for (int i = 0; i < 10; ++i) babs += fabsf(b1r[i]);
        const bool bias_zero = (babs == 0.0f);   // block-uniform

        const u64 siw = g_si[n * CC + tid];

        float f1 = 0.0f, dotp = 0.0f, v2 = 0.0f;
        float v1[10];
        #pragma unroll
        for (int i = 0; i < 10; ++i) v1[i] = 0.0f;

        #pragma unroll 1
        for (int cch = 0; cch < 4; ++cch) {
            unsigned sb16 = (unsigned)(siw >> (16 * cch));
            unsigned cb = 0u;
            if (bias_zero) {
                // exact: x + 0.0f == x for every value arising here
                #pragma unroll
                for (int tt = 0; tt < 16; ++tt) {
                    float sif = ((sb16 >> tt) & 1u) ? 1.0f : 0.0f;
                    f1 = fmaf(f1, 0.5f, sif);
                    float nv[10], cv[10];
                    bool  sq[10];
                    #pragma unroll
                    for (int i = 0; i < 10; ++i) nv[i] = fmaf(f1, w1r[i], v1[i]);
                    #pragma unroll
                    for (int i = 0; i < 10; ++i) sq[i] = (nv[i] >= 1.0f);
                    #pragma unroll
                    for (int i = 0; i < 10; ++i) v1[i] = sq[i] ? 0.0f : nv[i];
                    #pragma unroll
                    for (int i = 0; i < 10; ++i) cv[i] = sq[i] ? w2r[i] : 0.0f;
                    float s01 = cv[0] + cv[1], s23 = cv[2] + cv[3];
                    float s45 = cv[4] + cv[5], s67 = cv[6] + cv[7];
                    float s89 = cv[8] + cv[9];
                    float dsum = ((s01 + s23) + (s45 + s67)) + s89;
                    dotp = fmaf(dotp, 0.5f, dsum);      // = w2 . f2_t
                    v2 += dotp;
                    bool s2 = (v2 >= 1.0f);
                    v2 = s2 ? 0.0f : v2;
                    cb |= s2 ? (1u << tt) : 0u;
                }
            } else {
                #pragma unroll
                for (int tt = 0; tt < 16; ++tt) {
                    float sif = ((sb16 >> tt) & 1u) ? 1.0f : 0.0f;
                    f1 = fmaf(f1, 0.5f, sif);
                    float nv[10], cv[10];
                    bool  sq[10];
                    #pragma unroll
                    for (int i = 0; i < 10; ++i) nv[i] = fmaf(f1, w1r[i], v1[i]) + b1r[i];
                    #pragma unroll
                    for (int i = 0; i < 10; ++i) sq[i] = (nv[i] >= 1.0f);
                    #pragma unroll
                    for (int i = 0; i < 10; ++i) v1[i] = sq[i] ? 0.0f : nv[i];
                    #pragma unroll
                    for (int i = 0; i < 10; ++i) cv[i] = sq[i] ? w2r[i] : 0.0f;
                    float s01 = cv[0] + cv[1], s23 = cv[2] + cv[3];
                    float s45 = cv[4] + cv[5], s67 = cv[6] + cv[7];
                    float s89 = cv[8] + cv[9];
                    float dsum = ((s01 + s23) + (s45 + s67)) + s89;
                    dotp = fmaf(dotp, 0.5f, dsum);
                    v2 += dotp + b2v;
                    bool s2 = (v2 >= 1.0f);
                    v2 = s2 ? 0.0f : v2;
                    cb |= s2 ? (1u << tt) : 0u;
                }
            }
            // ---- ballot transpose: per-(warp,t) partial spike counts ----
            int mypc = 0;
            #pragma unroll
            for (int tt = 0; tt < 16; ++tt) {
                unsigned m = __ballot_sync(FULL, (cb >> tt) & 1u);
                if (lane == tt) mypc = __popc(m);
            }
            if (lane < 16) pcnt[cch][wid][lane] = mypc;
            BAR_ARRIVE(1 + cch, 160);
        }
    } else if (wid == 4) {
        // ---- serial h/q0 chain; counts assembled from 4 partials and
        //      broadcast via register shuffles (off the recurrence) ----
        const float sw0l = sw0[lane], sb0l = sb0[lane];
        float fsum = 0.0f, vs = 0.0f, q0 = 0.0f;
        #pragma unroll 1
        for (int cch = 0; cch < 4; ++cch) {
            BAR_SYNC(1 + cch, 160);
            int myc = 0;
            if (lane < 16)
                myc = pcnt[cch][0][lane] + pcnt[cch][1][lane]
                    + pcnt[cch][2][lane] + pcnt[cch][3][lane];
            float mycf = (float)myc;
            float cf[16];
            #pragma unroll
            for (int tt = 0; tt < 16; ++tt)
                cf[tt] = __shfl_sync(FULL, mycf, tt);     // off-chain
            #pragma unroll
            for (int tt = 0; tt < 16; ++tt) {
                int t = 16 * cch + tt;
                fsum = fmaf(fsum, 0.5f, cf[tt]);
                vs += fsum;
                bool s5 = (vs >= 1.0f);
                float hf = s5 ? 1.0f : 0.0f;
                vs = s5 ? 0.0f : vs;
                q0 += fmaf(hf, sw0l, sb0l);
                bool pA = (q0 >= 1.0f);
                unsigned m = __ballot_sync(FULL, pA);
                q0 = pA ? 0.0f : q0;
                if (lane == 0) sa_masks[t] = m;
            }
            BAR_ARRIVE(5 + cch, 96);
        }
    } else if (wid < 7) {
        // ---- t-parallel masked matvec, 8 timesteps per warp per chunk ----
        float r[32];
        #pragma unroll
        for (int k = 0; k < 32; ++k) r[k] = sw1s[lane * 33 + k];
        const int toff = (wid - 5) * 8;
        #pragma unroll 1
        for (int cch = 0; cch < 4; ++cch) {
            BAR_SYNC(5 + cch, 96);
            const int t0 = 16 * cch + toff;
            #pragma unroll
            for (int t = t0; t < t0 + 8; ++t) {
                unsigned m = sa_masks[t];
                float a0 = 0.0f, a1 = 0.0f, a2 = 0.0f, a3 = 0.0f;
                #pragma unroll
                for (int k = 0; k < 32; k += 4) {
                    if (m & (1u << k))       a0 += r[k];
                    if (m & (1u << (k + 1))) a1 += r[k + 1];
                    if (m & (1u << (k + 2))) a2 += r[k + 2];
                    if (m & (1u << (k + 3))) a3 += r[k + 3];
                }
                msb[t][lane] = (a0 + a1) + (a2 + a3);
            }
            BAR_ARRIVE(9 + cch, 96);
        }
    } else {
        // ---- serial dot/q1/g2/q2 chain; msb prefetched per chunk ----
        const float sb1l = sb1[lane], sw2l = sw2[lane];
        const float sb2v = (lane == 0) ? sb2[0] : 0.0f;
        float dot = 0.0f, q1 = 0.0f, g2 = 0.0f, q2p = 0.0f;
        #pragma unroll 1
        for (int cch = 0; cch < 4; ++cch) {
            BAR_SYNC(9 + cch, 96);
            float mv[16];
            #pragma unroll
            for (int tt = 0; tt < 16; ++tt)
                mv[tt] = msb[16 * cch + tt][lane];        // off-chain
            #pragma unroll
            for (int tt = 0; tt < 16; ++tt) {
                int t = 16 * cch + tt;
                dot = fmaf(dot, 0.5f, mv[tt]);   // = sw1 . g1_t
                q1 = q1 + dot + sb1l;
                bool pB = (q1 >= 1.0f);
                float sBf = pB ? 1.0f : 0.0f;
                q1 = pB ? 0.0f : q1;
                g2 = fmaf(g2, 0.5f, sBf);
                q2p = fmaf(g2, sw2l, q2p) + sb2v;
                qbuf[t][lane] = q2p;
            }
        }
    }
    __syncthreads();

    // ---- reduce per-lane q2 partials -> out (T,N,1) ----
    if (tid < 64) {
        int t = tid;
        float s = 0.0f;
        #pragma unroll
        for (int l = 0; l < 32; ++l) s += qbuf[t][l];
        out[t * NB + n] = s;
    }
}

// ---------------------------------------------------------------------------
extern "C" void kernel_launch(void* const* d_in, const int* in_sizes, int n_in,
                              void* d_out, int out_size)
{
    const float* x   = (const float*)d_in[0];
    const float* w1  = (const float*)d_in[1];
    const float* b1  = (const float*)d_in[2];
    const float* w2  = (const float*)d_in[3];
    const float* b2  = (const float*)d_in[4];
    const float* sw0 = (const float*)d_in[5];
    const float* sb0 = (const float*)d_in[6];
    const float* sw1 = (const float*)d_in[7];
    const float* sb1 = (const float*)d_in[8];
    const float* sw2 = (const float*)d_in[9];
    const float* sb2 = (const float*)d_in[10];
    float* out = (float*)d_out;

    k1_lif<<<512, 256>>>(x);
    k2k3<<<NB, 256>>>(w1, b1, w2, b2, sw0, sb0, sw1, sb1, sw2, sb2, out);
}

// round 17
// speedup vs baseline: 1.1978x; 1.1978x over previous
#include <cuda_runtime.h>
#include <cstdint>
#include <math.h>

#define TT 64
#define NB 32
#define CC 128
#define DD 64
#define NC (NB * CC)

typedef unsigned long long u64;

// per-(n,c): 64-bit integrator-spike word over t (si = any jeffress spike)
__device__ u64 g_si[NC];

#define BAR_ARRIVE(id, cnt) asm volatile("bar.arrive %0, %1;" :: "r"(id), "r"(cnt) : "memory")
#define BAR_SYNC(id, cnt)   asm volatile("bar.sync %0, %1;"   :: "r"(id), "r"(cnt) : "memory")

// ---------------------------------------------------------------------------
// K1 (R15 verbatim — best measured k1): warp per (n,c), per-t VOTE.ANY,
// flat 64-iteration u64 loop. Exact shortcut: every kint > 1 and the
// integrator IF hard-resets, so integrator spike si_t == (any unit spiked).
// Input fold: u = ab?2:(ao?1:0) with ao=a|d, ab=a&d — exact values.
// ---------------------------------------------------------------------------
__global__ void __launch_bounds__(256) k1_lif(const float* __restrict__ x)
{
    const unsigned FULL = 0xFFFFFFFFu;
    const int tid  = threadIdx.x;
    const int lane = tid & 31;
    const int wg   = (blockIdx.x * blockDim.x + tid) >> 5;  // nc
    const int n = wg >> 7;
    const int c = wg & (CC - 1);

    // pack input spikes: bit t of bx = x[t] != 0
    const int base = n * 2 * CC + c;
    const int strideT = NB * 2 * CC;
    unsigned lo0 = __ballot_sync(FULL, x[base + lane * strideT]             != 0.0f);
    unsigned hi0 = __ballot_sync(FULL, x[base + (lane + 32) * strideT]      != 0.0f);
    unsigned lo1 = __ballot_sync(FULL, x[base + CC + lane * strideT]        != 0.0f);
    unsigned hi1 = __ballot_sync(FULL, x[base + CC + (lane + 32) * strideT] != 0.0f);
    u64 bx0 = (u64)lo0 | ((u64)hi0 << 32);
    u64 bx1 = (u64)lo1 | ((u64)hi1 << 32);

    // unit j sees x0 delayed by j, x1 delayed by (D-1-j): pre-shift
    u64 a0 = bx0 << lane;            // unit j0 = lane
    u64 a1 = bx0 << (lane + 32);     // unit j1 = lane + 32
    u64 d0 = bx1 << (63 - lane);
    u64 d1 = bx1 << (31 - lane);

    // fold: sum of 2 bits -> OR/AND words
    u64 ao0 = a0 | d0, ab0 = a0 & d0;
    u64 ao1 = a1 | d1, ab1 = a1 & d1;

    float vj0 = 0.0f, vj1 = 0.0f;
    u64 siw = 0ull;

    #pragma unroll
    for (int t = 0; t < TT; ++t) {
        float u0 = ((ab0 >> t) & 1ull) ? 2.0f : (((ao0 >> t) & 1ull) ? 1.0f : 0.0f);
        float u1 = ((ab1 >> t) & 1ull) ? 2.0f : (((ao1 >> t) & 1ull) ? 1.0f : 0.0f);
        vj0 = fmaf(u0 - vj0, 0.05f, vj0);
        vj1 = fmaf(u1 - vj1, 0.05f, vj1);
        bool s0 = (vj0 >= 1.0f), s1 = (vj1 >= 1.0f);
        bool any = __any_sync(FULL, s0 | s1);
        vj0 = s0 ? 0.0f : vj0;
        vj1 = s1 ? 0.0f : vj1;
        siw |= any ? (1ull << t) : 0ull;
    }

    if (lane == 0) g_si[wg] = siw;
}

// ---------------------------------------------------------------------------
// K2K3 (R14 verbatim — best measured at 10.8-10.9us): one block per n, 256
// threads, warp-specialized chunk pipeline (chunk = 16 timesteps, 4 chunks).
// Barrier audit:
//   id 1+c : producers (warps 0-3) 128 arrive + warp 4 32 sync  = 160
//   id 5+c : warp 4 32 arrive + warps 5,6 64 sync               = 96
//   id 9+c : warps 5,6 64 arrive + warp 7 32 sync               = 96
// Producers emit per-(warp,t) partial spike counts via a 16-ballot
// transpose; Phase S dsum via select + balanced add tree (in registers).
// ---------------------------------------------------------------------------
__global__ void __launch_bounds__(256, 1) k2k3(
    const float* __restrict__ w1, const float* __restrict__ b1,
    const float* __restrict__ w2, const float* __restrict__ b2,
    const float* __restrict__ sw0, const float* __restrict__ sb0,
    const float* __restrict__ sw1, const float* __restrict__ sb1,
    const float* __restrict__ sw2, const float* __restrict__ sb2,
    float* __restrict__ out)
{
    __shared__ int pcnt[4][4][16];       // [chunk][producer warp][t]
    __shared__ unsigned sa_masks[TT];
    __shared__ float sw1s[32 * 33];
    __shared__ float msb[TT][33];
    __shared__ float qbuf[TT][33];

    const unsigned FULL = 0xFFFFFFFFu;
    const int n = blockIdx.x;
    const int tid = threadIdx.x;
    const int lane = tid & 31;
    const int wid = tid >> 5;

    #pragma unroll
    for (int i = tid; i < 1024; i += 256) {
        int row = i >> 5, col = i & 31;
        sw1s[row * 33 + col] = sw1[i];
    }
    __syncthreads();

    if (wid < 4) {
        // ---- Phase S producers: thread = channel (tid 0..127) ----
        float w1r[10], b1r[10], w2r[10];
        #pragma unroll
        for (int i = 0; i < 10; ++i) { w1r[i] = w1[i]; b1r[i] = b1[i]; w2r[i] = w2[i]; }
        const float b2v = b2[0];
        float babs = fabsf(b2v);
        #pragma unroll
        for (int i = 0; i < 10; ++i) babs += fabsf(b1r[i]);
        const bool bias_zero = (babs == 0.0f);   // block-uniform

        const u64 siw = g_si[n * CC + tid];

        float f1 = 0.0f, dotp = 0.0f, v2 = 0.0f;
        float v1[10];
        #pragma unroll
        for (int i = 0; i < 10; ++i) v1[i] = 0.0f;

        #pragma unroll 1
        for (int cch = 0; cch < 4; ++cch) {
            unsigned sb16 = (unsigned)(siw >> (16 * cch));
            unsigned cb = 0u;
            if (bias_zero) {
                // exact: x + 0.0f == x for every value arising here
                #pragma unroll
                for (int tt = 0; tt < 16; ++tt) {
                    float sif = ((sb16 >> tt) & 1u) ? 1.0f : 0.0f;
                    f1 = fmaf(f1, 0.5f, sif);
                    float nv[10], cv[10];
                    bool  sq[10];
                    #pragma unroll
                    for (int i = 0; i < 10; ++i) nv[i] = fmaf(f1, w1r[i], v1[i]);
                    #pragma unroll
                    for (int i = 0; i < 10; ++i) sq[i] = (nv[i] >= 1.0f);
                    #pragma unroll
                    for (int i = 0; i < 10; ++i) v1[i] = sq[i] ? 0.0f : nv[i];
                    #pragma unroll
                    for (int i = 0; i < 10; ++i) cv[i] = sq[i] ? w2r[i] : 0.0f;
                    float s01 = cv[0] + cv[1], s23 = cv[2] + cv[3];
                    float s45 = cv[4] + cv[5], s67 = cv[6] + cv[7];
                    float s89 = cv[8] + cv[9];
                    float dsum = ((s01 + s23) + (s45 + s67)) + s89;
                    dotp = fmaf(dotp, 0.5f, dsum);      // = w2 . f2_t
                    v2 += dotp;
                    bool s2 = (v2 >= 1.0f);
                    v2 = s2 ? 0.0f : v2;
                    cb |= s2 ? (1u << tt) : 0u;
                }
            } else {
                #pragma unroll
                for (int tt = 0; tt < 16; ++tt) {
                    float sif = ((sb16 >> tt) & 1u) ? 1.0f : 0.0f;
                    f1 = fmaf(f1, 0.5f, sif);
                    float nv[10], cv[10];
                    bool  sq[10];
                    #pragma unroll
                    for (int i = 0; i < 10; ++i) nv[i] = fmaf(f1, w1r[i], v1[i]) + b1r[i];
                    #pragma unroll
                    for (int i = 0; i < 10; ++i) sq[i] = (nv[i] >= 1.0f);
                    #pragma unroll
                    for (int i = 0; i < 10; ++i) v1[i] = sq[i] ? 0.0f : nv[i];
                    #pragma unroll
                    for (int i = 0; i < 10; ++i) cv[i] = sq[i] ? w2r[i] : 0.0f;
                    float s01 = cv[0] + cv[1], s23 = cv[2] + cv[3];
                    float s45 = cv[4] + cv[5], s67 = cv[6] + cv[7];
                    float s89 = cv[8] + cv[9];
                    float dsum = ((s01 + s23) + (s45 + s67)) + s89;
                    dotp = fmaf(dotp, 0.5f, dsum);
                    v2 += dotp + b2v;
                    bool s2 = (v2 >= 1.0f);
                    v2 = s2 ? 0.0f : v2;
                    cb |= s2 ? (1u << tt) : 0u;
                }
            }
            // ---- ballot transpose: per-(warp,t) partial spike counts ----
            int mypc = 0;
            #pragma unroll
            for (int tt = 0; tt < 16; ++tt) {
                unsigned m = __ballot_sync(FULL, (cb >> tt) & 1u);
                if (lane == tt) mypc = __popc(m);
            }
            if (lane < 16) pcnt[cch][wid][lane] = mypc;
            BAR_ARRIVE(1 + cch, 160);
        }
    } else if (wid == 4) {
        // ---- serial h/q0 chain; counts assembled from 4 partials and
        //      broadcast via register shuffles (off the recurrence) ----
        const float sw0l = sw0[lane], sb0l = sb0[lane];
        float fsum = 0.0f, vs = 0.0f, q0 = 0.0f;
        #pragma unroll 1
        for (int cch = 0; cch < 4; ++cch) {
            BAR_SYNC(1 + cch, 160);
            int myc = 0;
            if (lane < 16)
                myc = pcnt[cch][0][lane] + pcnt[cch][1][lane]
                    + pcnt[cch][2][lane] + pcnt[cch][3][lane];
            float mycf = (float)myc;
            float cf[16];
            #pragma unroll
            for (int tt = 0; tt < 16; ++tt)
                cf[tt] = __shfl_sync(FULL, mycf, tt);     // off-chain
            #pragma unroll
            for (int tt = 0; tt < 16; ++tt) {
                int t = 16 * cch + tt;
                fsum = fmaf(fsum, 0.5f, cf[tt]);
                vs += fsum;
                bool s5 = (vs >= 1.0f);
                float hf = s5 ? 1.0f : 0.0f;
                vs = s5 ? 0.0f : vs;
                q0 += fmaf(hf, sw0l, sb0l);
                bool pA = (q0 >= 1.0f);
                unsigned m = __ballot_sync(FULL, pA);
                q0 = pA ? 0.0f : q0;
                if (lane == 0) sa_masks[t] = m;
            }
            BAR_ARRIVE(5 + cch, 96);
        }
    } else if (wid < 7) {
        // ---- t-parallel masked matvec, 8 timesteps per warp per chunk ----
        float r[32];
        #pragma unroll
        for (int k = 0; k < 32; ++k) r[k] = sw1s[lane * 33 + k];
        const int toff = (wid - 5) * 8;
        #pragma unroll 1
        for (int cch = 0; cch < 4; ++cch) {
            BAR_SYNC(5 + cch, 96);
            const int t0 = 16 * cch + toff;
            #pragma unroll
            for (int t = t0; t < t0 + 8; ++t) {
                unsigned m = sa_masks[t];
                float a0 = 0.0f, a1 = 0.0f, a2 = 0.0f, a3 = 0.0f;
                #pragma unroll
                for (int k = 0; k < 32; k += 4) {
                    if (m & (1u << k))       a0 += r[k];
                    if (m & (1u << (k + 1))) a1 += r[k + 1];
                    if (m & (1u << (k + 2))) a2 += r[k + 2];
                    if (m & (1u << (k + 3))) a3 += r[k + 3];
                }
                msb[t][lane] = (a0 + a1) + (a2 + a3);
            }
            BAR_ARRIVE(9 + cch, 96);
        }
    } else {
        // ---- serial dot/q1/g2/q2 chain; msb prefetched per chunk ----
        const float sb1l = sb1[lane], sw2l = sw2[lane];
        const float sb2v = (lane == 0) ? sb2[0] : 0.0f;
        float dot = 0.0f, q1 = 0.0f, g2 = 0.0f, q2p = 0.0f;
        #pragma unroll 1
        for (int cch = 0; cch < 4; ++cch) {
            BAR_SYNC(9 + cch, 96);
            float mv[16];
            #pragma unroll
            for (int tt = 0; tt < 16; ++tt)
                mv[tt] = msb[16 * cch + tt][lane];        // off-chain
            #pragma unroll
            for (int tt = 0; tt < 16; ++tt) {
                int t = 16 * cch + tt;
                dot = fmaf(dot, 0.5f, mv[tt]);   // = sw1 . g1_t
                q1 = q1 + dot + sb1l;
                bool pB = (q1 >= 1.0f);
                float sBf = pB ? 1.0f : 0.0f;
                q1 = pB ? 0.0f : q1;
                g2 = fmaf(g2, 0.5f, sBf);
                q2p = fmaf(g2, sw2l, q2p) + sb2v;
                qbuf[t][lane] = q2p;
            }
        }
    }
    __syncthreads();

    // ---- reduce per-lane q2 partials -> out (T,N,1) ----
    if (tid < 64) {
        int t = tid;
        float s = 0.0f;
        #pragma unroll
        for (int l = 0; l < 32; ++l) s += qbuf[t][l];
        out[t * NB + n] = s;
    }
}

// ---------------------------------------------------------------------------
extern "C" void kernel_launch(void* const* d_in, const int* in_sizes, int n_in,
                              void* d_out, int out_size)
{
    const float* x   = (const float*)d_in[0];
    const float* w1  = (const float*)d_in[1];
    const float* b1  = (const float*)d_in[2];
    const float* w2  = (const float*)d_in[3];
    const float* b2  = (const float*)d_in[4];
    const float* sw0 = (const float*)d_in[5];
    const float* sb0 = (const float*)d_in[6];
    const float* sw1 = (const float*)d_in[7];
    const float* sb1 = (const float*)d_in[8];
    const float* sw2 = (const float*)d_in[9];
    const float* sb2 = (const float*)d_in[10];
    float* out = (float*)d_out;

    k1_lif<<<512, 256>>>(x);
    k2k3<<<NB, 256>>>(w1, b1, w2, b2, sw0, sb0, sw1, sb1, sw2, sb2, out);
}